// round 3
// baseline (speedup 1.0000x reference)
#include <cuda_runtime.h>
#include <cuda_bf16.h>
#include <cstdint>

// Problem constants
#define BB 2
#define LL 4096
#define DD 1024
#define HH 16
#define PP 4
#define DH 64
#define MM (BB*LL)   // 8192

// Scratch (device globals; no allocation at runtime)
__device__ float g_v[MM * DD];      // value projection (B,L,H*Dh)
__device__ float g_off[MM * 128];   // offset projection (B,L,H*P*2)
__device__ float g_attw[MM * 64];   // attention-weight logits (B,L,H*P)
__device__ float g_tmp[MM * DD];    // sampled output before w_out

// ---------------------------------------------------------------------------
// Tiled fp32 SGEMM with bias: C[M,N] = A[M,K] @ B[K,N] + bias[N]
// BM=128, BN=128, BK=8, 256 threads, 8x8 per-thread tile.
// M % 128 == 0, K % 8 == 0 assumed. N handled with guards (N in {1024,128,64}).
// ---------------------------------------------------------------------------
#define BM 128
#define BN 128
#define BK 8
#define TM 8
#define TN 8

__global__ __launch_bounds__(256) void sgemm_bias_kernel(
    int M, int N, int K,
    const float* __restrict__ A, const float* __restrict__ B,
    const float* __restrict__ bias, float* __restrict__ C)
{
    __shared__ float As[BK][BM];
    __shared__ float Bs[BK][BN];

    const int tid  = threadIdx.x;
    const int bRow = blockIdx.y * BM;
    const int bCol = blockIdx.x * BN;

    // A tile loads: 128 rows x 8 cols = 256 float4 (one per thread)
    const int aLdRow = tid >> 1;
    const int aLdCol = (tid & 1) << 2;
    // B tile loads: 8 rows x 128 cols = 256 float4
    const int bLdRow = tid >> 5;
    const int bLdCol = (tid & 31) << 2;

    const int trow = (tid >> 4) * TM;
    const int tcol = (tid & 15) * TN;

    float acc[TM][TN];
    #pragma unroll
    for (int i = 0; i < TM; i++)
        #pragma unroll
        for (int j = 0; j < TN; j++)
            acc[i][j] = 0.f;

    const float* Aptr = A + (size_t)(bRow + aLdRow) * K + aLdCol;

    for (int k0 = 0; k0 < K; k0 += BK) {
        float4 av = *reinterpret_cast<const float4*>(Aptr + k0);
        As[aLdCol + 0][aLdRow] = av.x;
        As[aLdCol + 1][aLdRow] = av.y;
        As[aLdCol + 2][aLdRow] = av.z;
        As[aLdCol + 3][aLdRow] = av.w;

        float4 bv = make_float4(0.f, 0.f, 0.f, 0.f);
        if (bCol + bLdCol < N)
            bv = *reinterpret_cast<const float4*>(
                B + (size_t)(k0 + bLdRow) * N + bCol + bLdCol);
        *reinterpret_cast<float4*>(&Bs[bLdRow][bLdCol]) = bv;

        __syncthreads();

        #pragma unroll
        for (int kk = 0; kk < BK; ++kk) {
            float ra[TM], rb[TN];
            #pragma unroll
            for (int i = 0; i < TM; i++) ra[i] = As[kk][trow + i];
            #pragma unroll
            for (int j = 0; j < TN; j++) rb[j] = Bs[kk][tcol + j];
            #pragma unroll
            for (int i = 0; i < TM; i++)
                #pragma unroll
                for (int j = 0; j < TN; j++)
                    acc[i][j] += ra[i] * rb[j];
        }
        __syncthreads();
    }

    #pragma unroll
    for (int i = 0; i < TM; i++) {
        const int row = bRow + trow + i;
        #pragma unroll
        for (int j = 0; j < TN; j += 4) {
            const int col = bCol + tcol + j;
            if (col < N) {
                float4 o;
                o.x = acc[i][j + 0] + bias[col + 0];
                o.y = acc[i][j + 1] + bias[col + 1];
                o.z = acc[i][j + 2] + bias[col + 2];
                o.w = acc[i][j + 3] + bias[col + 3];
                *reinterpret_cast<float4*>(C + (size_t)row * N + col) = o;
            }
        }
    }
}

// ---------------------------------------------------------------------------
// Deformable sampling: one warp per (b, l, h).
// tmp[b,l,h*64+d] = sum_p softmax(attw)[p] * bilinear_sample(v, p)[d]
// ---------------------------------------------------------------------------
__global__ __launch_bounds__(256) void sample_kernel(
    const float* __restrict__ v, const float* __restrict__ poff,
    const float* __restrict__ pattw, float* __restrict__ tmp)
{
    const int gwarp = (blockIdx.x * 256 + threadIdx.x) >> 5;
    const int lane  = threadIdx.x & 31;
    if (gwarp >= MM * HH) return;

    const int h   = gwarp & (HH - 1);
    const int row = gwarp >> 4;           // b*L + l
    const int b   = row >> 12;            // L = 4096
    const int l   = row & (LL - 1);

    float w0 = 0.f, w1 = 0.f;
    int xi0 = 0, xi1 = 0;

    if (lane < PP) {
        const int p = lane;
        float logit = pattw[(size_t)row * 64 + h * PP + p];
        float ox    = poff[(size_t)row * 128 + h * (PP * 2) + p * 2 + 0];
        float oy    = poff[(size_t)row * 128 + h * (PP * 2) + p * 2 + 1];

        // softmax over the 4 lanes 0..3
        float mx = logit;
        mx = fmaxf(mx, __shfl_xor_sync(0xf, mx, 1));
        mx = fmaxf(mx, __shfl_xor_sync(0xf, mx, 2));
        float e = expf(logit - mx);
        float s = e;
        s += __shfl_xor_sync(0xf, s, 1);
        s += __shfl_xor_sync(0xf, s, 2);
        float aw = e / s;

        // sampling coordinates (same op order as reference)
        float ry = (float)l / (float)(LL - 1);
        float sx = fminf(fmaxf(ox, 0.f), 1.f);
        float sy = fminf(fmaxf(ry + oy, 0.f), 1.f);
        float ix = ((sx + 1.f) * (float)LL - 1.f) * 0.5f;
        float iy = ((sy + 1.f) * 1.f - 1.f) * 0.5f;

        float x0f = floorf(ix);
        float fx  = ix - x0f;
        int   x0  = (int)x0f;
        int   x1  = x0 + 1;
        float m0  = (x0 >= 0 && x0 < LL) ? 1.f : 0.f;
        float m1  = (x1 >= 0 && x1 < LL) ? 1.f : 0.f;

        float y0f = floorf(iy);
        float fy  = iy - y0f;
        float hy  = (y0f == 0.f ? 1.f - fy : 0.f) + (y0f == -1.f ? fy : 0.f);

        w0 = aw * (1.f - fx) * m0 * hy;
        w1 = aw * fx * m1 * hy;
        xi0 = min(max(x0, 0), LL - 1);
        xi1 = min(max(x1, 0), LL - 1);
    }

    const float* vb = v + (size_t)b * LL * DD + h * DH + lane;
    float acc0 = 0.f, acc1 = 0.f;

    #pragma unroll
    for (int p = 0; p < PP; p++) {
        float W0 = __shfl_sync(0xffffffff, w0, p);
        float W1 = __shfl_sync(0xffffffff, w1, p);
        int   I0 = __shfl_sync(0xffffffff, xi0, p);
        int   I1 = __shfl_sync(0xffffffff, xi1, p);
        const float* r0 = vb + (size_t)I0 * DD;
        const float* r1 = vb + (size_t)I1 * DD;
        acc0 += W0 * r0[0]  + W1 * r1[0];
        acc1 += W0 * r0[32] + W1 * r1[32];
    }

    float* o = tmp + (size_t)row * DD + h * DH + lane;
    o[0]  = acc0;
    o[32] = acc1;
}

// ---------------------------------------------------------------------------
// Launch
// ---------------------------------------------------------------------------
extern "C" void kernel_launch(void* const* d_in, const int* in_sizes, int n_in,
                              void* d_out, int out_size)
{
    const float* query   = (const float*)d_in[0];
    // d_in[1] = key   (unused by the reference output)
    const float* value   = (const float*)d_in[2];
    // d_in[3,4] = w_qk, b_qk (dead code in the reference)
    const float* w_value = (const float*)d_in[5];
    const float* b_value = (const float*)d_in[6];
    const float* w_off   = (const float*)d_in[7];
    const float* b_off   = (const float*)d_in[8];
    const float* w_attw  = (const float*)d_in[9];
    const float* b_attw  = (const float*)d_in[10];
    const float* w_out   = (const float*)d_in[11];
    const float* b_out   = (const float*)d_in[12];
    float* out = (float*)d_out;

    float *v_p, *off_p, *attw_p, *tmp_p;
    cudaGetSymbolAddress((void**)&v_p,    g_v);
    cudaGetSymbolAddress((void**)&off_p,  g_off);
    cudaGetSymbolAddress((void**)&attw_p, g_attw);
    cudaGetSymbolAddress((void**)&tmp_p,  g_tmp);

    const dim3 gridBig(DD / BN, MM / BM);   // (8, 64)
    const dim3 gridSmall(1, MM / BM);       // (1, 64)

    // v = value @ w_value + b_value
    sgemm_bias_kernel<<<gridBig, 256>>>(MM, DD, DD, value, w_value, b_value, v_p);
    // off = query @ w_off + b_off      (N = 128)
    sgemm_bias_kernel<<<gridSmall, 256>>>(MM, 128, DD, query, w_off, b_off, off_p);
    // attw logits = query @ w_attw + b_attw  (N = 64)
    sgemm_bias_kernel<<<gridSmall, 256>>>(MM, 64, DD, query, w_attw, b_attw, attw_p);
    // deformable sampling
    const int nWarps = MM * HH;             // 131072
    sample_kernel<<<nWarps / 8, 256>>>(v_p, off_p, attw_p, tmp_p);
    // out = tmp @ w_out + b_out
    sgemm_bias_kernel<<<gridBig, 256>>>(MM, DD, DD, tmp_p, w_out, b_out, out);
}

// round 4
// speedup vs baseline: 1.4211x; 1.4211x over previous
#include <cuda_runtime.h>
#include <cuda_bf16.h>
#include <cstdint>

// Problem constants
#define BB 2
#define LL 4096
#define DD 1024
#define HH 16
#define PP 4
#define DH 64
#define MM (BB*LL)   // 8192

// Scratch (device globals; no allocation at runtime)
__device__ float g_v[MM * DD];      // value projection
__device__ float g_off[MM * 128];   // offset projection
__device__ float g_attw[MM * 64];   // attention-weight logits
__device__ float g_tmp[MM * DD];    // sampled output before w_out

// ---------------------------------------------------------------------------
// tf32 helpers
// ---------------------------------------------------------------------------
__device__ __forceinline__ uint32_t f2tf32(float x) {
    uint32_t r;
    asm("cvt.rna.tf32.f32 %0, %1;" : "=r"(r) : "f"(x));
    return r;
}

__device__ __forceinline__ void mma_tf32(float c[4], const uint32_t a[4], const uint32_t b[2]) {
    asm volatile(
        "mma.sync.aligned.m16n8k8.row.col.f32.tf32.tf32.f32 "
        "{%0,%1,%2,%3}, {%4,%5,%6,%7}, {%8,%9}, {%0,%1,%2,%3};"
        : "+f"(c[0]), "+f"(c[1]), "+f"(c[2]), "+f"(c[3])
        : "r"(a[0]), "r"(a[1]), "r"(a[2]), "r"(a[3]),
          "r"(b[0]), "r"(b[1]));
}

// ---------------------------------------------------------------------------
// 3xTF32 tensor-core GEMM: C[M,1024] = A[M,1024] @ B[1024,1024] + bias
// Block 128x128, BK=16, 256 threads (8 warps), warp tile 64x32.
// Accuracy ~fp32 via (a_lo*b_hi + a_hi*b_lo + a_hi*b_hi).
// ---------------------------------------------------------------------------
#define SSTR 136   // smem row stride in floats (conflict-free frag loads)

__global__ __launch_bounds__(256, 2) void gemm_tf32x3_kernel(
    const float* __restrict__ A, const float* __restrict__ B,
    const float* __restrict__ bias, float* __restrict__ C)
{
    __shared__ float Ah[16 * SSTR];
    __shared__ float Al[16 * SSTR];
    __shared__ float Bh[16 * SSTR];
    __shared__ float Bl[16 * SSTR];

    const int tid  = threadIdx.x;
    const int lane = tid & 31;
    const int warp = tid >> 5;
    const int wm = (warp >> 2) * 64;    // warp M offset: 0 or 64
    const int wn = (warp & 3) * 32;     // warp N offset: 0..96
    const int g = lane >> 2;            // group id 0..7
    const int t = lane & 3;             // thread in group 0..3

    const int bRow = blockIdx.y * 128;
    const int bCol = blockIdx.x * 128;

    // global-load indexing
    const int arow = tid >> 1;          // 0..127
    const int acol = (tid & 1) * 8;     // 0 or 8
    const int bkr  = tid >> 5;          // 0..7
    const int bnc  = (tid & 31) * 4;    // 0..124

    float acc[4][4][4];
    #pragma unroll
    for (int i = 0; i < 4; i++)
        #pragma unroll
        for (int j = 0; j < 4; j++)
            #pragma unroll
            for (int r = 0; r < 4; r++)
                acc[i][j][r] = 0.f;

    const float* Abase = A + (size_t)(bRow + arow) * DD;

    for (int k0 = 0; k0 < DD; k0 += 16) {
        // --- load + split A tile (128 x 16), store transposed As[k][m] ---
        #pragma unroll
        for (int h = 0; h < 2; h++) {
            float4 v = *reinterpret_cast<const float4*>(Abase + k0 + acol + h * 4);
            float xs[4] = {v.x, v.y, v.z, v.w};
            #pragma unroll
            for (int j = 0; j < 4; j++) {
                int kk = acol + h * 4 + j;
                float hf = __uint_as_float(f2tf32(xs[j]));
                Ah[kk * SSTR + arow] = hf;
                Al[kk * SSTR + arow] = __uint_as_float(f2tf32(xs[j] - hf));
            }
        }
        // --- load + split B tile (16 x 128), store Bs[k][n] ---
        #pragma unroll
        for (int p = 0; p < 2; p++) {
            int kk = bkr + p * 8;
            float4 v = *reinterpret_cast<const float4*>(
                B + (size_t)(k0 + kk) * DD + bCol + bnc);
            float xs[4] = {v.x, v.y, v.z, v.w};
            #pragma unroll
            for (int j = 0; j < 4; j++) {
                float hf = __uint_as_float(f2tf32(xs[j]));
                Bh[kk * SSTR + bnc + j] = hf;
                Bl[kk * SSTR + bnc + j] = __uint_as_float(f2tf32(xs[j] - hf));
            }
        }
        __syncthreads();

        #pragma unroll
        for (int ks = 0; ks < 2; ks++) {
            const int kb = ks * 8;
            uint32_t afh[4][4], afl[4][4], bfh[4][2], bfl[4][2];
            #pragma unroll
            for (int i = 0; i < 4; i++) {
                const int m0 = wm + i * 16;
                afh[i][0] = __float_as_uint(Ah[(kb + t)     * SSTR + m0 + g]);
                afh[i][1] = __float_as_uint(Ah[(kb + t)     * SSTR + m0 + g + 8]);
                afh[i][2] = __float_as_uint(Ah[(kb + t + 4) * SSTR + m0 + g]);
                afh[i][3] = __float_as_uint(Ah[(kb + t + 4) * SSTR + m0 + g + 8]);
                afl[i][0] = __float_as_uint(Al[(kb + t)     * SSTR + m0 + g]);
                afl[i][1] = __float_as_uint(Al[(kb + t)     * SSTR + m0 + g + 8]);
                afl[i][2] = __float_as_uint(Al[(kb + t + 4) * SSTR + m0 + g]);
                afl[i][3] = __float_as_uint(Al[(kb + t + 4) * SSTR + m0 + g + 8]);
            }
            #pragma unroll
            for (int j = 0; j < 4; j++) {
                const int n0 = wn + j * 8;
                bfh[j][0] = __float_as_uint(Bh[(kb + t)     * SSTR + n0 + g]);
                bfh[j][1] = __float_as_uint(Bh[(kb + t + 4) * SSTR + n0 + g]);
                bfl[j][0] = __float_as_uint(Bl[(kb + t)     * SSTR + n0 + g]);
                bfl[j][1] = __float_as_uint(Bl[(kb + t + 4) * SSTR + n0 + g]);
            }
            #pragma unroll
            for (int i = 0; i < 4; i++)
                #pragma unroll
                for (int j = 0; j < 4; j++) {
                    mma_tf32(acc[i][j], afl[i], bfh[j]);   // lo terms first
                    mma_tf32(acc[i][j], afh[i], bfl[j]);
                    mma_tf32(acc[i][j], afh[i], bfh[j]);   // dominant last
                }
        }
        __syncthreads();
    }

    // epilogue: c0:(g,2t) c1:(g,2t+1) c2:(g+8,2t) c3:(g+8,2t+1)
    #pragma unroll
    for (int i = 0; i < 4; i++) {
        const int r0 = bRow + wm + i * 16 + g;
        const int r1 = r0 + 8;
        #pragma unroll
        for (int j = 0; j < 4; j++) {
            const int col = bCol + wn + j * 8 + 2 * t;
            const float bz0 = bias[col], bz1 = bias[col + 1];
            float2 o0 = make_float2(acc[i][j][0] + bz0, acc[i][j][1] + bz1);
            float2 o1 = make_float2(acc[i][j][2] + bz0, acc[i][j][3] + bz1);
            *reinterpret_cast<float2*>(C + (size_t)r0 * DD + col) = o0;
            *reinterpret_cast<float2*>(C + (size_t)r1 * DD + col) = o1;
        }
    }
}

// ---------------------------------------------------------------------------
// Fused exact-fp32 small projections (BIT-CRITICAL: k-ascending FMA chain must
// match the reference GEMM — offsets are amplified ~2048x by grid_sample).
// blockIdx.x: 0,1 -> off cols [0,64),[64,128);  2 -> attw cols [0,64)
// ---------------------------------------------------------------------------
__global__ __launch_bounds__(256) void proj_small_kernel(
    const float* __restrict__ Q,
    const float* __restrict__ w_off,  const float* __restrict__ b_off,
    const float* __restrict__ w_attw, const float* __restrict__ b_attw,
    float* __restrict__ off_out, float* __restrict__ attw_out)
{
    __shared__ float As[8][128];
    __shared__ float Bs[8][64];

    const int tid  = threadIdx.x;
    const int bx   = blockIdx.x;
    const int bRow = blockIdx.y * 128;
    const bool isOff = (bx < 2);
    const float* Bm   = isOff ? w_off  : w_attw;
    const float* bias = isOff ? b_off  : b_attw;
    float* Cp         = isOff ? off_out : attw_out;
    const int NB      = isOff ? 128 : 64;     // B / C row stride
    const int colBase = isOff ? bx * 64 : 0;

    const int arow = tid >> 1;
    const int acol = (tid & 1) * 4;
    const int bkr  = tid >> 5;            // 0..7
    const int bnc2 = (tid & 31) * 2;      // 0..62

    const int trow = (tid >> 4) * 8;
    const int tcol = (tid & 15) * 4;

    float acc[8][4];
    #pragma unroll
    for (int i = 0; i < 8; i++)
        #pragma unroll
        for (int j = 0; j < 4; j++)
            acc[i][j] = 0.f;

    const float* Qbase = Q + (size_t)(bRow + arow) * DD;

    for (int k0 = 0; k0 < DD; k0 += 8) {
        float4 av = *reinterpret_cast<const float4*>(Qbase + k0 + acol);
        As[acol + 0][arow] = av.x;
        As[acol + 1][arow] = av.y;
        As[acol + 2][arow] = av.z;
        As[acol + 3][arow] = av.w;

        float2 bv = *reinterpret_cast<const float2*>(
            Bm + (size_t)(k0 + bkr) * NB + colBase + bnc2);
        Bs[bkr][bnc2 + 0] = bv.x;
        Bs[bkr][bnc2 + 1] = bv.y;
        __syncthreads();

        #pragma unroll
        for (int kk = 0; kk < 8; kk++) {
            float ra[8], rb[4];
            #pragma unroll
            for (int i = 0; i < 8; i++) ra[i] = As[kk][trow + i];
            #pragma unroll
            for (int j = 0; j < 4; j++) rb[j] = Bs[kk][tcol + j];
            #pragma unroll
            for (int i = 0; i < 8; i++)
                #pragma unroll
                for (int j = 0; j < 4; j++)
                    acc[i][j] += ra[i] * rb[j];
        }
        __syncthreads();
    }

    #pragma unroll
    for (int i = 0; i < 8; i++) {
        const int row = bRow + trow + i;
        #pragma unroll
        for (int j = 0; j < 4; j++) {
            const int col = tcol + j;
            Cp[(size_t)row * NB + colBase + col] = acc[i][j] + bias[colBase + col];
        }
    }
}

// ---------------------------------------------------------------------------
// Deformable sampling: one warp per (b, l, h).
// ---------------------------------------------------------------------------
__global__ __launch_bounds__(256) void sample_kernel(
    const float* __restrict__ v, const float* __restrict__ poff,
    const float* __restrict__ pattw, float* __restrict__ tmp)
{
    const int gwarp = (blockIdx.x * 256 + threadIdx.x) >> 5;
    const int lane  = threadIdx.x & 31;
    if (gwarp >= MM * HH) return;

    const int h   = gwarp & (HH - 1);
    const int row = gwarp >> 4;
    const int b   = row >> 12;
    const int l   = row & (LL - 1);

    float w0 = 0.f, w1 = 0.f;
    int xi0 = 0, xi1 = 0;

    if (lane < PP) {
        const int p = lane;
        float logit = pattw[(size_t)row * 64 + h * PP + p];
        float ox    = poff[(size_t)row * 128 + h * (PP * 2) + p * 2 + 0];
        float oy    = poff[(size_t)row * 128 + h * (PP * 2) + p * 2 + 1];

        float mx = logit;
        mx = fmaxf(mx, __shfl_xor_sync(0xf, mx, 1));
        mx = fmaxf(mx, __shfl_xor_sync(0xf, mx, 2));
        float e = expf(logit - mx);
        float s = e;
        s += __shfl_xor_sync(0xf, s, 1);
        s += __shfl_xor_sync(0xf, s, 2);
        float aw = e / s;

        float ry = (float)l / (float)(LL - 1);
        float sx = fminf(fmaxf(ox, 0.f), 1.f);
        float sy = fminf(fmaxf(ry + oy, 0.f), 1.f);
        float ix = ((sx + 1.f) * (float)LL - 1.f) * 0.5f;
        float iy = ((sy + 1.f) * 1.f - 1.f) * 0.5f;

        float x0f = floorf(ix);
        float fx  = ix - x0f;
        int   x0  = (int)x0f;
        int   x1  = x0 + 1;
        float m0  = (x0 >= 0 && x0 < LL) ? 1.f : 0.f;
        float m1  = (x1 >= 0 && x1 < LL) ? 1.f : 0.f;

        float y0f = floorf(iy);
        float fy  = iy - y0f;
        float hy  = (y0f == 0.f ? 1.f - fy : 0.f) + (y0f == -1.f ? fy : 0.f);

        w0 = aw * (1.f - fx) * m0 * hy;
        w1 = aw * fx * m1 * hy;
        xi0 = min(max(x0, 0), LL - 1);
        xi1 = min(max(x1, 0), LL - 1);
    }

    const float* vb = v + (size_t)b * LL * DD + h * DH + lane;
    float acc0 = 0.f, acc1 = 0.f;

    #pragma unroll
    for (int p = 0; p < PP; p++) {
        float W0 = __shfl_sync(0xffffffff, w0, p);
        float W1 = __shfl_sync(0xffffffff, w1, p);
        int   I0 = __shfl_sync(0xffffffff, xi0, p);
        int   I1 = __shfl_sync(0xffffffff, xi1, p);
        const float* r0 = vb + (size_t)I0 * DD;
        const float* r1 = vb + (size_t)I1 * DD;
        acc0 += W0 * r0[0]  + W1 * r1[0];
        acc1 += W0 * r0[32] + W1 * r1[32];
    }

    float* o = tmp + (size_t)row * DD + h * DH + lane;
    o[0]  = acc0;
    o[32] = acc1;
}

// ---------------------------------------------------------------------------
// Launch
// ---------------------------------------------------------------------------
extern "C" void kernel_launch(void* const* d_in, const int* in_sizes, int n_in,
                              void* d_out, int out_size)
{
    const float* query   = (const float*)d_in[0];
    const float* value   = (const float*)d_in[2];
    const float* w_value = (const float*)d_in[5];
    const float* b_value = (const float*)d_in[6];
    const float* w_off   = (const float*)d_in[7];
    const float* b_off   = (const float*)d_in[8];
    const float* w_attw  = (const float*)d_in[9];
    const float* b_attw  = (const float*)d_in[10];
    const float* w_out   = (const float*)d_in[11];
    const float* b_out   = (const float*)d_in[12];
    float* out = (float*)d_out;

    float *v_p, *off_p, *attw_p, *tmp_p;
    cudaGetSymbolAddress((void**)&v_p,    g_v);
    cudaGetSymbolAddress((void**)&off_p,  g_off);
    cudaGetSymbolAddress((void**)&attw_p, g_attw);
    cudaGetSymbolAddress((void**)&tmp_p,  g_tmp);

    const dim3 gridBig(DD / 128, MM / 128);   // (8, 64)
    const dim3 gridProj(3, MM / 128);         // (3, 64)

    // v = value @ w_value + b_value   (3xTF32 tensor cores)
    gemm_tf32x3_kernel<<<gridBig, 256>>>(value, w_value, b_value, v_p);
    // off / attw projections (exact fp32, bit-critical)
    proj_small_kernel<<<gridProj, 256>>>(query, w_off, b_off, w_attw, b_attw,
                                         off_p, attw_p);
    // deformable sampling
    sample_kernel<<<(MM * HH) / 8, 256>>>(v_p, off_p, attw_p, tmp_p);
    // out = tmp @ w_out + b_out       (3xTF32 tensor cores)
    gemm_tf32x3_kernel<<<gridBig, 256>>>(tmp_p, w_out, b_out, out);
}

// round 6
// speedup vs baseline: 2.6090x; 1.8359x over previous
#include <cuda_runtime.h>
#include <cuda_bf16.h>
#include <cstdint>

// Problem constants
#define LL 4096
#define DD 1024
#define HH 16
#define PP 4
#define DH 64
#define MM 8192   // B*L

// ---------------------------------------------------------------------------
// Scratch (device globals; no runtime allocation)
// ---------------------------------------------------------------------------
__device__ float         g_v[MM * DD];      // value projection (fp32)
__device__ float         g_off[MM * 128];   // offset projection (exact fp32)
__device__ float         g_attw[MM * 64];   // attention logits (exact fp32)
__device__ __nv_bfloat16 g_ah[MM * DD];     // A operand hi (bf16 split), [M][K]
__device__ __nv_bfloat16 g_al[MM * DD];     // A operand lo
__device__ __nv_bfloat16 g_bh[DD * DD];     // B operand hi, [N][K] (K-major)
__device__ __nv_bfloat16 g_bl[DD * DD];     // B operand lo

// ---------------------------------------------------------------------------
// helpers
// ---------------------------------------------------------------------------
__device__ __forceinline__ uint32_t smem_u32(const void* p) {
    uint32_t a;
    asm("{ .reg .u64 t; cvta.to.shared.u64 t, %1; cvt.u32.u64 %0, t; }" : "=r"(a) : "l"(p));
    return a;
}
__device__ __forceinline__ void cp_async16(uint32_t saddr, const void* gaddr) {
    asm volatile("cp.async.cg.shared.global [%0], [%1], 16;" :: "r"(saddr), "l"(gaddr) : "memory");
}
#define CP_COMMIT()  asm volatile("cp.async.commit_group;" ::: "memory")
#define CP_WAIT(n)   asm volatile("cp.async.wait_group %0;" :: "n"(n) : "memory")

__device__ __forceinline__ void mma_bf16(float c[4], const uint32_t a[4], const uint32_t b[2]) {
    asm volatile(
        "mma.sync.aligned.m16n8k16.row.col.f32.bf16.bf16.f32 "
        "{%0,%1,%2,%3}, {%4,%5,%6,%7}, {%8,%9}, {%0,%1,%2,%3};"
        : "+f"(c[0]), "+f"(c[1]), "+f"(c[2]), "+f"(c[3])
        : "r"(a[0]), "r"(a[1]), "r"(a[2]), "r"(a[3]),
          "r"(b[0]), "r"(b[1]));
}

__device__ __forceinline__ void bsplit(float x, __nv_bfloat16& h, __nv_bfloat16& l) {
    h = __float2bfloat16(x);
    l = __float2bfloat16(x - __bfloat162float(h));
}

// ---------------------------------------------------------------------------
// Elementwise split: fp32 [R x 1024] -> bf16 hi/lo, same layout
// ---------------------------------------------------------------------------
__global__ __launch_bounds__(256) void split_a_kernel(
    const float4* __restrict__ X, __nv_bfloat162* __restrict__ H, __nv_bfloat162* __restrict__ L)
{
    const int g = blockIdx.x * 256 + threadIdx.x;   // MM*DD/4 threads
    float4 v = X[g];
    __nv_bfloat16 h0, l0, h1, l1, h2, l2, h3, l3;
    bsplit(v.x, h0, l0); bsplit(v.y, h1, l1);
    bsplit(v.z, h2, l2); bsplit(v.w, h3, l3);
    H[2 * g + 0] = __nv_bfloat162(h0, h1);
    H[2 * g + 1] = __nv_bfloat162(h2, h3);
    L[2 * g + 0] = __nv_bfloat162(l0, l1);
    L[2 * g + 1] = __nv_bfloat162(l2, l3);
}

// ---------------------------------------------------------------------------
// Transpose + split: W[K=1024][N=1024] fp32 -> BH/BL[N][K] bf16
// ---------------------------------------------------------------------------
__global__ __launch_bounds__(256) void split_bT_kernel(
    const float* __restrict__ W, __nv_bfloat16* __restrict__ BH, __nv_bfloat16* __restrict__ BL)
{
    __shared__ float t[32][33];
    const int tx = threadIdx.x, ty = threadIdx.y;       // (32, 8)
    const int n = blockIdx.x * 32 + tx;
    const int k = blockIdx.y * 32 + ty;
    #pragma unroll
    for (int i = 0; i < 4; i++)
        t[ty + 8 * i][tx] = W[(size_t)(k + 8 * i) * DD + n];
    __syncthreads();
    const int ko = blockIdx.y * 32 + tx;
    const int no = blockIdx.x * 32 + ty;
    #pragma unroll
    for (int i = 0; i < 4; i++) {
        float v = t[tx][ty + 8 * i];
        __nv_bfloat16 h, l;
        bsplit(v, h, l);
        BH[(size_t)(no + 8 * i) * DD + ko] = h;
        BL[(size_t)(no + 8 * i) * DD + ko] = l;
    }
}

// ---------------------------------------------------------------------------
// bf16x3 mma.sync GEMM: C[M,1024] = (Ah+Al) @ (Bh+Bl)^T + bias
// Tile 128x128, BK=32 (16 bf16 pairs), 2-stage cp.async double buffer.
// 8 warps, warp tile 64x32, mma m16n8k16.
// smem regions per stage: Ah, Al, Bh, Bl each [128 rows][20 u32] (pairs 0..15 + pad)
// ---------------------------------------------------------------------------
#define RSTR     20                 // row stride in u32 (16 pairs + 4 pad) => conflict-free
#define REG_ELE  (128 * RSTR)       // 2560 u32 per region
#define STG_ELE  (4 * REG_ELE)      // 10240 u32 per stage
#define SMEM_G   (2 * STG_ELE * 4)  // 81920 bytes

__global__ __launch_bounds__(256, 2) void gemm_bf16x3_kernel(
    const __nv_bfloat16* __restrict__ Ah, const __nv_bfloat16* __restrict__ Al,
    const __nv_bfloat16* __restrict__ Bh, const __nv_bfloat16* __restrict__ Bl,
    const float* __restrict__ bias, float* __restrict__ C)
{
    extern __shared__ uint32_t S[];
    const uint32_t sb = smem_u32(S);

    const int tid = threadIdx.x, lane = tid & 31, warp = tid >> 5;
    const int wm = (warp >> 2) * 64;    // warp M offset
    const int wn = (warp & 3) * 32;     // warp N offset
    const int g = lane >> 2, t = lane & 3;
    const int bRow = blockIdx.y * 128, bCol = blockIdx.x * 128;

    const __nv_bfloat16* gptr[4] = {
        Ah + (size_t)bRow * DD, Al + (size_t)bRow * DD,
        Bh + (size_t)bCol * DD, Bl + (size_t)bCol * DD };

    float acc[4][4][4];
    #pragma unroll
    for (int i = 0; i < 4; i++)
        #pragma unroll
        for (int j = 0; j < 4; j++)
            #pragma unroll
            for (int r = 0; r < 4; r++)
                acc[i][j][r] = 0.f;

    // issue loads for chunk c into stage buf
    auto issue = [&](int c, int buf) {
        const uint32_t sbase = sb + buf * (STG_ELE * 4);
        #pragma unroll
        for (int i = 0; i < 8; i++) {
            const int v = tid + 256 * i;        // 0..2047
            const int reg = v >> 9;             // 0..3
            const int u = v & 511;
            const int row = u >> 2;             // 0..127
            const int p4 = u & 3;               // 16B group (4 pairs)
            cp_async16(sbase + reg * (REG_ELE * 4) + row * (RSTR * 4) + p4 * 16,
                       gptr[reg] + (size_t)row * DD + c * 32 + p4 * 8);
        }
        CP_COMMIT();
    };

    issue(0, 0);

    for (int c = 0; c < 32; c++) {
        if (c + 1 < 32) { issue(c + 1, (c + 1) & 1); CP_WAIT(1); }
        else            { CP_WAIT(0); }
        __syncthreads();

        const uint32_t* st = S + (c & 1) * STG_ELE;
        const uint32_t* sAh = st;
        const uint32_t* sAl = st + REG_ELE;
        const uint32_t* sBh = st + 2 * REG_ELE;
        const uint32_t* sBl = st + 3 * REG_ELE;

        #pragma unroll
        for (int ks = 0; ks < 2; ks++) {
            const int kp = ks * 8;  // pair base for this k16 step
            uint32_t afh[4][4], afl[4][4], bfh[4][2], bfl[4][2];
            #pragma unroll
            for (int i = 0; i < 4; i++) {
                const int m0 = wm + i * 16;
                afh[i][0] = sAh[(m0 + g)     * RSTR + kp + t];
                afh[i][1] = sAh[(m0 + g + 8) * RSTR + kp + t];
                afh[i][2] = sAh[(m0 + g)     * RSTR + kp + t + 4];
                afh[i][3] = sAh[(m0 + g + 8) * RSTR + kp + t + 4];
                afl[i][0] = sAl[(m0 + g)     * RSTR + kp + t];
                afl[i][1] = sAl[(m0 + g + 8) * RSTR + kp + t];
                afl[i][2] = sAl[(m0 + g)     * RSTR + kp + t + 4];
                afl[i][3] = sAl[(m0 + g + 8) * RSTR + kp + t + 4];
            }
            #pragma unroll
            for (int j = 0; j < 4; j++) {
                const int n0 = wn + j * 8;
                bfh[j][0] = sBh[(n0 + g) * RSTR + kp + t];
                bfh[j][1] = sBh[(n0 + g) * RSTR + kp + t + 4];
                bfl[j][0] = sBl[(n0 + g) * RSTR + kp + t];
                bfl[j][1] = sBl[(n0 + g) * RSTR + kp + t + 4];
            }
            #pragma unroll
            for (int i = 0; i < 4; i++)
                #pragma unroll
                for (int j = 0; j < 4; j++) {
                    mma_bf16(acc[i][j], afl[i], bfh[j]);
                    mma_bf16(acc[i][j], afh[i], bfl[j]);
                    mma_bf16(acc[i][j], afh[i], bfh[j]);
                }
        }
        __syncthreads();
    }

    // epilogue: c0:(g,2t) c1:(g,2t+1) c2:(g+8,2t) c3:(g+8,2t+1)
    #pragma unroll
    for (int i = 0; i < 4; i++) {
        const int r0 = bRow + wm + i * 16 + g;
        const int r1 = r0 + 8;
        #pragma unroll
        for (int j = 0; j < 4; j++) {
            const int col = bCol + wn + j * 8 + 2 * t;
            const float bz0 = bias[col], bz1 = bias[col + 1];
            float2 o0 = make_float2(acc[i][j][0] + bz0, acc[i][j][1] + bz1);
            float2 o1 = make_float2(acc[i][j][2] + bz0, acc[i][j][3] + bz1);
            *reinterpret_cast<float2*>(C + (size_t)r0 * DD + col) = o0;
            *reinterpret_cast<float2*>(C + (size_t)r1 * DD + col) = o1;
        }
    }
}

// ---------------------------------------------------------------------------
// Exact-fp32 projections (BIT-CRITICAL: per-output k-ascending FMA chain,
// identical to the reference chain). BK=16, BM=64. grid (3, 128).
// bx 0,1 -> off col halves; bx 2 -> attw.
// ---------------------------------------------------------------------------
__global__ __launch_bounds__(256) void proj_kernel(
    const float* __restrict__ Q,
    const float* __restrict__ w_off,  const float* __restrict__ b_off,
    const float* __restrict__ w_attw, const float* __restrict__ b_attw,
    float* __restrict__ off_out, float* __restrict__ attw_out)
{
    __shared__ float As[16][64];   // [k][m]
    __shared__ float Bs[16][64];   // [k][n]

    const int tid = threadIdx.x;
    const int bx  = blockIdx.x;
    const int bRow = blockIdx.y * 64;
    const bool isOff = (bx < 2);
    const float* Bm   = isOff ? w_off : w_attw;
    const float* bias = isOff ? b_off : b_attw;
    float* Cp         = isOff ? off_out : attw_out;
    const int NB      = isOff ? 128 : 64;
    const int colBase = isOff ? bx * 64 : 0;

    const int arow = tid >> 2;          // 0..63
    const int acol = (tid & 3) * 4;     // 0,4,8,12
    const int bkr  = tid >> 4;          // 0..15
    const int bnc  = (tid & 15) * 4;    // 0..60
    const int trow = (tid >> 4) * 4;
    const int tcol = (tid & 15) * 4;

    float acc[4][4];
    #pragma unroll
    for (int i = 0; i < 4; i++)
        #pragma unroll
        for (int j = 0; j < 4; j++)
            acc[i][j] = 0.f;

    const float* Qbase = Q + (size_t)(bRow + arow) * DD;

    for (int k0 = 0; k0 < DD; k0 += 16) {
        float4 av = *reinterpret_cast<const float4*>(Qbase + k0 + acol);
        As[acol + 0][arow] = av.x;
        As[acol + 1][arow] = av.y;
        As[acol + 2][arow] = av.z;
        As[acol + 3][arow] = av.w;
        float4 bv = *reinterpret_cast<const float4*>(
            Bm + (size_t)(k0 + bkr) * NB + colBase + bnc);
        Bs[bkr][bnc + 0] = bv.x;
        Bs[bkr][bnc + 1] = bv.y;
        Bs[bkr][bnc + 2] = bv.z;
        Bs[bkr][bnc + 3] = bv.w;
        __syncthreads();

        #pragma unroll
        for (int kk = 0; kk < 16; kk++) {
            float4 ra = *reinterpret_cast<const float4*>(&As[kk][trow]);
            float4 rb = *reinterpret_cast<const float4*>(&Bs[kk][tcol]);
            float a[4] = {ra.x, ra.y, ra.z, ra.w};
            float b[4] = {rb.x, rb.y, rb.z, rb.w};
            #pragma unroll
            for (int i = 0; i < 4; i++)
                #pragma unroll
                for (int j = 0; j < 4; j++)
                    acc[i][j] += a[i] * b[j];
        }
        __syncthreads();
    }

    #pragma unroll
    for (int i = 0; i < 4; i++) {
        const int row = bRow + trow + i;
        #pragma unroll
        for (int j = 0; j < 4; j++) {
            const int col = tcol + j;
            Cp[(size_t)row * NB + colBase + col] = acc[i][j] + bias[colBase + col];
        }
    }
}

// ---------------------------------------------------------------------------
// Deformable sampling -> bf16 hi/lo split output (A operand for GEMM2)
// ---------------------------------------------------------------------------
__global__ __launch_bounds__(256) void sample_kernel(
    const float* __restrict__ v, const float* __restrict__ poff,
    const float* __restrict__ pattw,
    __nv_bfloat16* __restrict__ oh, __nv_bfloat16* __restrict__ ol)
{
    const int gwarp = (blockIdx.x * 256 + threadIdx.x) >> 5;
    const int lane  = threadIdx.x & 31;
    if (gwarp >= MM * HH) return;

    const int h   = gwarp & (HH - 1);
    const int row = gwarp >> 4;
    const int b   = row >> 12;
    const int l   = row & (LL - 1);

    float w0 = 0.f, w1 = 0.f;
    int xi0 = 0, xi1 = 0;

    if (lane < PP) {
        const int p = lane;
        float logit = pattw[(size_t)row * 64 + h * PP + p];
        float ox    = poff[(size_t)row * 128 + h * (PP * 2) + p * 2 + 0];
        float oy    = poff[(size_t)row * 128 + h * (PP * 2) + p * 2 + 1];

        float mx = logit;
        mx = fmaxf(mx, __shfl_xor_sync(0xf, mx, 1));
        mx = fmaxf(mx, __shfl_xor_sync(0xf, mx, 2));
        float e = expf(logit - mx);
        float s = e;
        s += __shfl_xor_sync(0xf, s, 1);
        s += __shfl_xor_sync(0xf, s, 2);
        float aw = e / s;

        float ry = (float)l / (float)(LL - 1);
        float sx = fminf(fmaxf(ox, 0.f), 1.f);
        float sy = fminf(fmaxf(ry + oy, 0.f), 1.f);
        float ix = ((sx + 1.f) * (float)LL - 1.f) * 0.5f;
        float iy = ((sy + 1.f) * 1.f - 1.f) * 0.5f;

        float x0f = floorf(ix);
        float fx  = ix - x0f;
        int   x0  = (int)x0f;
        int   x1  = x0 + 1;
        float m0  = (x0 >= 0 && x0 < LL) ? 1.f : 0.f;
        float m1  = (x1 >= 0 && x1 < LL) ? 1.f : 0.f;

        float y0f = floorf(iy);
        float fy  = iy - y0f;
        float hy  = (y0f == 0.f ? 1.f - fy : 0.f) + (y0f == -1.f ? fy : 0.f);

        w0 = aw * (1.f - fx) * m0 * hy;
        w1 = aw * fx * m1 * hy;
        xi0 = min(max(x0, 0), LL - 1);
        xi1 = min(max(x1, 0), LL - 1);
    }

    const float* vb = v + (size_t)b * LL * DD + h * DH + lane;
    float acc0 = 0.f, acc1 = 0.f;

    #pragma unroll
    for (int p = 0; p < PP; p++) {
        float W0 = __shfl_sync(0xffffffff, w0, p);
        float W1 = __shfl_sync(0xffffffff, w1, p);
        int   I0 = __shfl_sync(0xffffffff, xi0, p);
        int   I1 = __shfl_sync(0xffffffff, xi1, p);
        const float* r0 = vb + (size_t)I0 * DD;
        const float* r1 = vb + (size_t)I1 * DD;
        acc0 += W0 * r0[0]  + W1 * r1[0];
        acc1 += W0 * r0[32] + W1 * r1[32];
    }

    __nv_bfloat16 h0, l0, h1, l1;
    bsplit(acc0, h0, l0);
    bsplit(acc1, h1, l1);
    const size_t o = (size_t)row * DD + h * DH + lane;
    oh[o]      = h0;  ol[o]      = l0;
    oh[o + 32] = h1;  ol[o + 32] = l1;
}

// ---------------------------------------------------------------------------
// Launch
// ---------------------------------------------------------------------------
extern "C" void kernel_launch(void* const* d_in, const int* in_sizes, int n_in,
                              void* d_out, int out_size)
{
    const float* query   = (const float*)d_in[0];
    const float* value   = (const float*)d_in[2];
    const float* w_value = (const float*)d_in[5];
    const float* b_value = (const float*)d_in[6];
    const float* w_off   = (const float*)d_in[7];
    const float* b_off   = (const float*)d_in[8];
    const float* w_attw  = (const float*)d_in[9];
    const float* b_attw  = (const float*)d_in[10];
    const float* w_out   = (const float*)d_in[11];
    const float* b_out   = (const float*)d_in[12];
    float* out = (float*)d_out;

    float *v_p, *off_p, *attw_p;
    __nv_bfloat16 *ah_p, *al_p, *bh_p, *bl_p;
    cudaGetSymbolAddress((void**)&v_p,    g_v);
    cudaGetSymbolAddress((void**)&off_p,  g_off);
    cudaGetSymbolAddress((void**)&attw_p, g_attw);
    cudaGetSymbolAddress((void**)&ah_p,   g_ah);
    cudaGetSymbolAddress((void**)&al_p,   g_al);
    cudaGetSymbolAddress((void**)&bh_p,   g_bh);
    cudaGetSymbolAddress((void**)&bl_p,   g_bl);

    cudaFuncSetAttribute(gemm_bf16x3_kernel,
                         cudaFuncAttributeMaxDynamicSharedMemorySize, SMEM_G);

    const dim3 gridGemm(DD / 128, MM / 128);  // (8, 64)
    const dim3 gridT(DD / 32, DD / 32);
    const dim3 blkT(32, 8);

    // 1) operand prep for GEMM1
    split_bT_kernel<<<gridT, blkT>>>(w_value, bh_p, bl_p);
    split_a_kernel<<<MM * DD / 4 / 256, 256>>>(
        (const float4*)value, (__nv_bfloat162*)ah_p, (__nv_bfloat162*)al_p);
    // 2) v = value @ w_value + b  (bf16x3 mma.sync)
    gemm_bf16x3_kernel<<<gridGemm, 256, SMEM_G>>>(ah_p, al_p, bh_p, bl_p, b_value, v_p);
    // 3) exact-fp32 projections
    proj_kernel<<<dim3(3, MM / 64), 256>>>(query, w_off, b_off, w_attw, b_attw, off_p, attw_p);
    // 4) sampling -> bf16 split A for GEMM2
    sample_kernel<<<(MM * HH) / 8, 256>>>(v_p, off_p, attw_p, ah_p, al_p);
    // 5) operand prep for GEMM2
    split_bT_kernel<<<gridT, blkT>>>(w_out, bh_p, bl_p);
    // 6) out = tmp @ w_out + b  (bf16x3 mma.sync)
    gemm_bf16x3_kernel<<<gridGemm, 256, SMEM_G>>>(ah_p, al_p, bh_p, bl_p, b_out, out);
}